// round 7
// baseline (speedup 1.0000x reference)
#include <cuda_runtime.h>
#include <cuda_fp16.h>
#include <cstdint>

// ============================================================================
// LearnedClassVectors fused fp16 GEMM (M=65536, K=512, N=768), mma.sync.
// R7: decouple A-build from compute critical path.
//   - 3-buffer A ring: compute stage ks from buf[ks%3] while building stage
//     ks+2 into buf[(ks+2)%3]; per-stage barrier now guards a 2-stage-old
//     dependency (R6 showed issue=36%, tensor=51%, L1 26% idle -> latency
//     bound, not throughput bound).
//   - A-build interleaved one-voxel-per-k16-step under the MMAs.
//   - x prefetched one full stage ahead of its build.
//   B fragments via direct LDG.64 from fragment-native g_Wf (unchanged R6).
// ============================================================================

static __device__ __forceinline__ uint32_t smem_u32(const void* p) {
    uint32_t a;
    asm("{ .reg .u64 t; cvta.to.shared.u64 t, %1; cvt.u32.u64 %0, t; }"
        : "=r"(a) : "l"(p));
    return a;
}

#define LDS128(r0, r1, r2, r3, addr) \
    asm volatile("ld.shared.v4.u32 {%0, %1, %2, %3}, [%4];" \
                 : "=r"(r0), "=r"(r1), "=r"(r2), "=r"(r3) : "r"(addr))
#define STS128(r0, r1, r2, r3, addr) \
    asm volatile("st.shared.v4.b32 [%0], {%1, %2, %3, %4};" \
                 :: "r"(addr), "r"(r0), "r"(r1), "r"(r2), "r"(r3) : "memory")

#define LDSM_X4(r0, r1, r2, r3, addr) \
    asm volatile("ldmatrix.sync.aligned.m8n8.x4.shared.b16 {%0, %1, %2, %3}, [%4];" \
                 : "=r"(r0), "=r"(r1), "=r"(r2), "=r"(r3) : "r"(addr))

#define MMA16816S(c, a, b0, b1)                                               \
    asm volatile(                                                             \
        "mma.sync.aligned.m16n8k16.row.col.f32.f16.f16.f32 "                  \
        "{%0, %1, %2, %3}, {%4, %5, %6, %7}, {%8, %9}, {%0, %1, %2, %3};"     \
        : "+f"((c)[0]), "+f"((c)[1]), "+f"((c)[2]), "+f"((c)[3])              \
        : "r"((a)[0]), "r"((a)[1]), "r"((a)[2]), "r"((a)[3]),                 \
          "r"(b0), "r"(b1))

// SW128 swizzle for the A tiles (128B rows)
static __device__ __forceinline__ uint32_t swz(uint32_t base, uint32_t row, uint32_t koff) {
    return base + row * 128u + (koff ^ ((row & 7u) * 16u));
}

// ---------------- problem constants ----------------
static constexpr int N_TOTAL = 768;
static constexpr int K_TOTAL = 512;
static constexpr int N_TILES = 6;             // 768 / 128
static constexpr int M_TILES = 512;

// SMEM: LUT + 3-buffer A ring (B never touches smem)
static constexpr int SMEM_LUT = 0;                    // 13 x 16B fp16 vectors
static constexpr int SMEM_A0  = 1024;                 // 3 x (128 x 128B)
static constexpr int SMEM_BYTES = SMEM_A0 + 3 * 16384;  // 50176

// Fragment-native fp16 weights: blocks (bn in 0..95, bk in 0..31), each block
// = 8n x 16k stored as 32 lanes x uint2 = exactly the m16n8k16 B fragment:
//   lane l: b0 = {w[n][k0+2j], w[n][k0+2j+1]}, b1 = same at k+8,
//   n = bn*8 + l/4, j = l%4, k0 = bk*16.
__device__ __align__(16) uint2 g_Wf[96 * 32 * 32];

__global__ void __launch_bounds__(256) convert_w_kernel(const float* __restrict__ w)
{
    const int idx = blockIdx.x * 256 + threadIdx.x;     // 0 .. 98303
    const int l   = idx & 31;
    const int blk = idx >> 5;                           // bn*32 + bk
    const int bk  = blk & 31;
    const int bn  = blk >> 5;
    const int n   = bn * 8 + (l >> 2);
    const int k0  = bk * 16 + 2 * (l & 3);
    const float* wr = w + (size_t)n * K_TOTAL + k0;
    __half2 p0 = __floats2half2_rn(wr[0], wr[1]);
    __half2 p1 = __floats2half2_rn(wr[8], wr[9]);
    uint2 v;
    v.x = *reinterpret_cast<uint32_t*>(&p0);
    v.y = *reinterpret_cast<uint32_t*>(&p1);
    g_Wf[idx] = v;
}

// bucket = count(x >= iv_i)  ==  searchsorted(side='right')
static __device__ __forceinline__ int hu_bucket(float v)
{
    int b = 0;
    b += (v >= -1000.0f); b += (v >= -900.0f); b += (v >= -400.0f);
    b += (v >= -100.0f);  b += (v >= -50.0f);  b += (v >= -10.0f);
    b += (v >= 20.0f);    b += (v >= 40.0f);   b += (v >= 60.0f);
    b += (v >= 100.0f);   b += (v >= 800.0f);  b += (v >= 1000.0f);
    return b;
}

// ---------------- main fused kernel ----------------
__global__ void __launch_bounds__(256, 2) lcv_gemm_kernel(
    const float* __restrict__ x,        // [2,1,128,128,128]
    const float* __restrict__ vectors,  // [13,8]
    const float* __restrict__ fc_b,     // [768]
    float* __restrict__ out)            // [2,768,32,32,32]
{
    extern __shared__ __align__(1024) char smem[];
    const uint32_t sb = smem_u32(smem);
    const int tid = threadIdx.x;
    const int lane = tid & 31;
    const int warp = tid >> 5;

    // nt fastest so the 6 CTAs sharing an x-slice are L2-adjacent
    const int nt = blockIdx.x % N_TILES;
    const int mt = blockIdx.x / N_TILES;
    const int m0 = mt << 7;
    const int n0 = nt << 7;
    const int bidx = m0 >> 15;
    const int s0 = m0 & 32767;
    const int gd = s0 >> 10;
    const int gh0 = (s0 >> 5) & 31;

    // warp layout: 2 (M) x 4 (N); warp tile 64 x 32
    const int warp_m = (warp >> 2) * 64;
    const int warp_n = (warp & 3) * 32;

    // vectors LUT -> fp16 smem (13 rows x 16B)
    if (tid < 104) {
        __half h = __float2half_rn(vectors[tid]);
        *reinterpret_cast<__half*>(smem + SMEM_LUT + (tid >> 3) * 16 + (tid & 7) * 2) = h;
    }

    const uint32_t lut_base = sb + SMEM_LUT;

    // A-build mapping: thread owns patch-row r, one ph of the stage pair
    const int r = tid >> 1;
    const int ph_off = tid & 1;
    const int gh = gh0 + (r >> 5);
    const int gw = r & 31;
    const float* xb = x + (size_t)bidx * 2097152;
    // x address for stage s: pd = s>>1, ph = 2*(s&1)+ph_off
    // -> addr = base + pd*2^14 + (2*(s&1))*2^7   (base covers gh<<2 + ph_off)
    const float* xrow = xb + (((size_t)gd << 2) << 14)
                           + (((gh << 2) + ph_off) << 7) + (gw << 2);
    const uint32_t a_dst_koff = (uint32_t)(ph_off * 64);

    // A ldmatrix per-lane constants
    const uint32_t a_row_l = (uint32_t)(warp_m + (lane & 7) + ((lane >> 3) & 1) * 8);
    const uint32_t a_kc16  = (uint32_t)((lane >> 4) * 16);

    // B fragment pointer (ni stride 1024 uint2, kk stride 32 uint2)
    const uint2* bp = g_Wf + ((size_t)(n0 / 8 + (warp & 3) * 4) * 32) * 32 + lane;

    float acc4[4][4][4];
    #pragma unroll
    for (int mi = 0; mi < 4; mi++)
        #pragma unroll
        for (int ni = 0; ni < 4; ni++)
            #pragma unroll
            for (int k = 0; k < 4; k++) acc4[mi][ni][k] = 0.0f;

    __syncthreads();   // LUT visible to builds

    // helper lambda-ish macro: x address for stage s
    #define XLOAD(s) (*reinterpret_cast<const float4*>( \
        xrow + (((size_t)((s) >> 1)) << 14) + (((s) & 1) << 8)))
    // note: (2*(s&1))<<7 == (s&1)<<8

    const uint32_t abuf[3] = {sb + SMEM_A0, sb + SMEM_A0 + 16384, sb + SMEM_A0 + 32768};

    // ---------- prologue: build stages 0 and 1; preload x for stage 2 ----------
    float voxp[4];   // x for the NEXT build (stage ks+2 at loop iter ks)
    {
        #pragma unroll
        for (int s = 0; s < 2; s++) {
            const float4 xv = XLOAD(s);
            float vx[4] = {xv.x, xv.y, xv.z, xv.w};
            #pragma unroll
            for (int pw = 0; pw < 4; pw++) {
                int bkt = hu_bucket(vx[pw]);
                uint32_t q0, q1, q2, q3;
                LDS128(q0, q1, q2, q3, lut_base + (uint32_t)bkt * 16);
                STS128(q0, q1, q2, q3,
                       swz(abuf[s], (uint32_t)r, a_dst_koff + (uint32_t)(pw * 16)));
            }
        }
        const float4 xv = XLOAD(2);
        voxp[0] = xv.x; voxp[1] = xv.y; voxp[2] = xv.z; voxp[3] = xv.w;
        __syncthreads();
    }

    // B prefetch for kk=0
    uint2 bf[2][4];
    #pragma unroll
    for (int ni = 0; ni < 4; ni++)
        bf[0][ni] = __ldg(bp + (size_t)ni * 1024);

    // ---------- main loop: 8 stages; compute buf[ks%3], build stage ks+2 ----------
    #pragma unroll 1
    for (int ks = 0; ks < 8; ks++) {
        const bool build = (ks + 2 < 8);
        float vox[4];
        vox[0] = voxp[0]; vox[1] = voxp[1]; vox[2] = voxp[2]; vox[3] = voxp[3];

        // prefetch x for the build at ks+1 (stage ks+3): one full stage of cover
        if (ks + 3 < 8) {
            const float4 xv = XLOAD(ks + 3);
            voxp[0] = xv.x; voxp[1] = xv.y; voxp[2] = xv.z; voxp[3] = xv.w;
        }

        const uint32_t abase = abuf[ks % 3];
        const uint32_t abld  = abuf[(ks + 2) % 3];

        #pragma unroll
        for (int q = 0; q < 4; q++) {
            const int kk = ks * 4 + q;
            const int cur = kk & 1;
            // prefetch B fragments for kk+1
            if (kk + 1 < 32) {
                #pragma unroll
                for (int ni = 0; ni < 4; ni++)
                    bf[cur ^ 1][ni] = __ldg(bp + (size_t)ni * 1024 + (size_t)(kk + 1) * 32);
            }
            // A fragments for this k16
            const uint32_t koffA = (uint32_t)(q * 32) + a_kc16;
            uint32_t af[4][4];
            #pragma unroll
            for (int mi = 0; mi < 4; mi++) {
                LDSM_X4(af[mi][0], af[mi][1], af[mi][2], af[mi][3],
                        swz(abase, a_row_l + (uint32_t)(mi * 16), koffA));
            }
            #pragma unroll
            for (int ni = 0; ni < 4; ni++) {
                const uint32_t b0 = bf[cur][ni].x;
                const uint32_t b1 = bf[cur][ni].y;
                #pragma unroll
                for (int mi = 0; mi < 4; mi++)
                    MMA16816S(acc4[mi][ni], af[mi], b0, b1);
            }
            // interleave one voxel of the stage-(ks+2) build under the MMAs
            if (build) {
                int bkt = hu_bucket(vox[q]);
                uint32_t q0, q1, q2, q3;
                LDS128(q0, q1, q2, q3, lut_base + (uint32_t)bkt * 16);
                STS128(q0, q1, q2, q3,
                       swz(abld, (uint32_t)r, a_dst_koff + (uint32_t)(q * 16)));
            }
        }

        // barrier only while builds are still in flight (ks <= 5); it guards
        // a buffer whose consumers finished a full stage ago -> minimal wait.
        if (ks < 6) __syncthreads();
    }
    #undef XLOAD

    // ---------- epilogue ----------
    // fragment c0=(m=l/4, n=2(l%4)), c1=(m, n+1), c2=(m+8, n), c3=(m+8, n+1)
    {
        float* ob = out + (size_t)bidx * N_TOTAL * 32768 + (size_t)s0;
        const int mrow = warp_m + (lane >> 2);
        const int ncol = n0 + warp_n + 2 * (lane & 3);
        #pragma unroll
        for (int mi = 0; mi < 4; mi++) {
            const int m_t = mrow + mi * 16;
            #pragma unroll
            for (int ni = 0; ni < 4; ni++) {
                const int o0 = ncol + ni * 8;
                const float2 bv = *reinterpret_cast<const float2*>(fc_b + o0);
                ob[(size_t)o0 * 32768 + m_t]           = acc4[mi][ni][0] + bv.x;
                ob[(size_t)(o0 + 1) * 32768 + m_t]     = acc4[mi][ni][1] + bv.y;
                ob[(size_t)o0 * 32768 + m_t + 8]       = acc4[mi][ni][2] + bv.x;
                ob[(size_t)(o0 + 1) * 32768 + m_t + 8] = acc4[mi][ni][3] + bv.y;
            }
        }
    }
}

// ---------------- launch ----------------
extern "C" void kernel_launch(void* const* d_in, const int* in_sizes, int n_in,
                              void* d_out, int out_size)
{
    (void)in_sizes; (void)n_in; (void)out_size;
    const float* x       = (const float*)d_in[0];  // [2,1,128,128,128]
    const float* vectors = (const float*)d_in[1];  // [13,8]
    const float* fc_w    = (const float*)d_in[2];  // [768,512]
    const float* fc_b    = (const float*)d_in[3];  // [768]
    float* out = (float*)d_out;                    // [2,768,32,32,32]

    cudaFuncSetAttribute(lcv_gemm_kernel,
                         cudaFuncAttributeMaxDynamicSharedMemorySize, SMEM_BYTES);

    convert_w_kernel<<<96 * 32 * 32 / 256, 256>>>(fc_w);
    lcv_gemm_kernel<<<M_TILES * N_TILES, 256, SMEM_BYTES>>>(x, vectors, fc_b, out);
}